// round 8
// baseline (speedup 1.0000x reference)
#include <cuda_runtime.h>
#include <cstdint>

// out[src] += feat[dst] * w    ; feat [N,64] f32, E=1e6, N=1e5
// 2-launch pipeline:
//   k_build : persistent (98 blocks x 1024 thr, all resident) fused
//             hist -> grid-barrier -> scan -> grid-barrier -> scatter
//   k_accum : atomic-free per-node accumulation, 16 lanes/node
//
// Inputs: d_in[0]=feat f32[N*64], d_in[1]=ew f32[E],
//         d_in[2]=esrc i32[E],    d_in[3]=edst i32[E]

#define MAXN 100000
#define MAXE 1000000
#define NB 98            // ceil(MAXN/1024); NB < 148 SMs -> all blocks resident
#define BUILD_THREADS 1024

__device__ int    g_cnt[MAXN];        // zero at entry (zero-init; scan resets)
__device__ int    g_start[MAXN + 1];
__device__ int    g_cursor[MAXN];
__device__ float2 g_edge[MAXE];       // .x = __int_as_float(dst), .y = w
__device__ int    g_agg[NB];
__device__ unsigned g_tick[2];        // monotonic barrier tickets (replay-safe)

// Replay-safe grid barrier: monotonic ticket counter, no reset needed.
__device__ __forceinline__ void grid_barrier(int which, int nb) {
    __syncthreads();
    if (threadIdx.x == 0) {
        __threadfence();                              // release prior writes
        unsigned ticket = atomicAdd(&g_tick[which], 1);
        unsigned target = (ticket / nb + 1) * nb;
        while (atomicAdd(&g_tick[which], 0) < target) { }
    }
    __syncthreads();
}

__global__ __launch_bounds__(BUILD_THREADS, 1) void k_build(
    const int4*   __restrict__ esrc4,
    const int4*   __restrict__ edst4,
    const float4* __restrict__ ew4,
    const int*    __restrict__ esrc,
    int n_edges4, int n)
{
    int b = blockIdx.x, t = threadIdx.x;
    int gtid   = b * BUILD_THREADS + t;
    int stride = NB * BUILD_THREADS;

    // ---- phase 1: degree histogram (grid-stride, vectorized) ----
    for (int i = gtid; i < n_edges4; i += stride) {
        int4 s = __ldg(&esrc4[i]);
        atomicAdd(&g_cnt[s.x], 1);
        atomicAdd(&g_cnt[s.y], 1);
        atomicAdd(&g_cnt[s.z], 1);
        atomicAdd(&g_cnt[s.w], 1);
    }
    grid_barrier(0, NB);

    // ---- phase 2: exclusive scan of counts -> g_start / g_cursor ----
    __shared__ int warp_sum[32];
    __shared__ int s_pref;
    int lane = t & 31, w = t >> 5;
    int i = gtid;                       // one node per thread (98*1024 >= n)

    int v = 0;
    if (i < n) { v = __ldcg(&g_cnt[i]); g_cnt[i] = 0; }   // consume + reset

    int x = v;
    #pragma unroll
    for (int off = 1; off < 32; off <<= 1) {
        int y = __shfl_up_sync(0xffffffff, x, off);
        if (lane >= off) x += y;
    }
    if (lane == 31) warp_sum[w] = x;
    if (t == 0) s_pref = 0;
    __syncthreads();

    if (w == 0) {
        int ws = warp_sum[lane];
        int z = ws;
        #pragma unroll
        for (int off = 1; off < 32; off <<= 1) {
            int y = __shfl_up_sync(0xffffffff, z, off);
            if (lane >= off) z += y;
        }
        warp_sum[lane] = z - ws;                 // exclusive warp offsets
        if (lane == 31) g_agg[b] = z;            // block aggregate
    }
    grid_barrier(1, NB);                          // aggregates now visible

    if (t < b) atomicAdd(&s_pref, __ldcg(&g_agg[t]));
    __syncthreads();
    int P = s_pref;

    if (i < n) {
        int start = P + warp_sum[w] + (x - v);
        g_start[i]  = start;
        g_cursor[i] = start;
        if (i == n - 1) g_start[n] = start + v;
    }
    grid_barrier(0, NB);                          // cursors ready

    // ---- phase 3: scatter (dst, w) into CSR order ----
    for (int j = gtid; j < n_edges4; j += stride) {
        int4   s  = __ldg(&esrc4[j]);
        int4   d  = __ldg(&edst4[j]);
        float4 wt = __ldg(&ew4[j]);
        int p0 = atomicAdd(&g_cursor[s.x], 1);
        int p1 = atomicAdd(&g_cursor[s.y], 1);
        int p2 = atomicAdd(&g_cursor[s.z], 1);
        int p3 = atomicAdd(&g_cursor[s.w], 1);
        g_edge[p0] = make_float2(__int_as_float(d.x), wt.x);
        g_edge[p1] = make_float2(__int_as_float(d.y), wt.y);
        g_edge[p2] = make_float2(__int_as_float(d.z), wt.z);
        g_edge[p3] = make_float2(__int_as_float(d.w), wt.w);
    }
}

// 16 lanes per node, unroll-2 with next-pair prefetch; 8 blocks/SM.
__global__ __launch_bounds__(256, 8) void k_accum(const float* __restrict__ feat,
                                                  float* __restrict__ out,
                                                  int n_nodes) {
    int gid  = blockIdx.x * blockDim.x + threadIdx.x;
    int node = gid >> 4;
    int lane = gid & 15;
    if (node >= n_nodes) return;

    int beg = __ldg(&g_start[node]);
    int end = __ldg(&g_start[node + 1]);

    float4 acc = make_float4(0.f, 0.f, 0.f, 0.f);
    int j = beg;

    if (j + 1 < end) {
        float2 e0 = __ldg(&g_edge[j]);
        float2 e1 = __ldg(&g_edge[j + 1]);
        for (; j + 3 < end; j += 2) {
            float2 n0 = __ldg(&g_edge[j + 2]);
            float2 n1 = __ldg(&g_edge[j + 3]);
            const float4* r0 = reinterpret_cast<const float4*>(feat + (__float_as_int(e0.x) << 6));
            const float4* r1 = reinterpret_cast<const float4*>(feat + (__float_as_int(e1.x) << 6));
            float4 v0 = __ldg(&r0[lane]);
            float4 v1 = __ldg(&r1[lane]);
            acc.x += v0.x * e0.y + v1.x * e1.y;
            acc.y += v0.y * e0.y + v1.y * e1.y;
            acc.z += v0.z * e0.y + v1.z * e1.y;
            acc.w += v0.w * e0.y + v1.w * e1.y;
            e0 = n0; e1 = n1;
        }
        const float4* r0 = reinterpret_cast<const float4*>(feat + (__float_as_int(e0.x) << 6));
        const float4* r1 = reinterpret_cast<const float4*>(feat + (__float_as_int(e1.x) << 6));
        float4 v0 = __ldg(&r0[lane]);
        float4 v1 = __ldg(&r1[lane]);
        acc.x += v0.x * e0.y + v1.x * e1.y;
        acc.y += v0.y * e0.y + v1.y * e1.y;
        acc.z += v0.z * e0.y + v1.z * e1.y;
        acc.w += v0.w * e0.y + v1.w * e1.y;
        j += 2;
    }
    if (j < end) {
        float2 e0 = __ldg(&g_edge[j]);
        const float4* r0 = reinterpret_cast<const float4*>(feat + (__float_as_int(e0.x) << 6));
        float4 v0 = __ldg(&r0[lane]);
        acc.x += v0.x * e0.y;
        acc.y += v0.y * e0.y;
        acc.z += v0.z * e0.y;
        acc.w += v0.w * e0.y;
    }
    reinterpret_cast<float4*>(out + ((long long)node << 6))[lane] = acc;
}

extern "C" void kernel_launch(void* const* d_in, const int* in_sizes, int n_in,
                              void* d_out, int out_size)
{
    const float* feat = (const float*)d_in[0];
    const float* ew   = (const float*)d_in[1];
    const int*   esrc = (const int*)d_in[2];
    const int*   edst = (const int*)d_in[3];
    float*       out  = (float*)d_out;

    int n_edges  = in_sizes[1];
    int n_nodes  = out_size / 64;
    int n_edges4 = n_edges / 4;   // E divisible by 4

    k_build<<<NB, BUILD_THREADS>>>((const int4*)esrc, (const int4*)edst,
                                   (const float4*)ew, esrc, n_edges4, n_nodes);

    long long total = (long long)n_nodes * 16;
    k_accum<<<(int)((total + 255) / 256), 256>>>(feat, out, n_nodes);
}